// round 2
// baseline (speedup 1.0000x reference)
#include <cuda_runtime.h>
#include <math.h>

// Problem constants (fixed shapes from reference setup_inputs)
#define B_DIM   16
#define D_DIM   256
#define H_DIM   32
#define W_DIM   32
#define HW      1024            // H*W
#define N_Q     16384           // B*H*W
#define K_CODES 8192
#define Z_ELEMS 4194304         // B*D*H*W
#define BETA    0.25f

// Output layout (flattened tuple, float32):
// [0, 4194304)              z_q_st   (B,D,H,W)
// [4194304]                 vq_loss
// [4194305, 4194305+16384)  indices  (B,H,W) as float
// [4210689]                 perplexity
#define OFF_LOSS 4194304
#define OFF_IDX  4194305
#define OFF_PLX  4210689

// GEMM tiling
#define BM 64    // queries per block
#define BN 128   // codes per tile
#define BK 64    // k-chunk
#define TM 4
#define TN 8
#define NTHREADS 256

// Dynamic smem layout: As[256][64] + Bs[64][128] + en[128] + zn[64]
#define SMEM_AS_FLOATS (D_DIM * BM)        // 16384
#define SMEM_BS_FLOATS (BK * BN)           // 8192
#define SMEM_TOTAL_FLOATS (SMEM_AS_FLOATS + SMEM_BS_FLOATS + BN + BM)
#define SMEM_BYTES (SMEM_TOTAL_FLOATS * 4) // 99072 B

// Scratch (no cudaMalloc allowed)
__device__ float  g_enorm[K_CODES];
__device__ float  g_znorm[N_Q];
__device__ int    g_bestidx[N_Q];
__device__ int    g_counts[K_CODES];
__device__ double g_mse;

// ---------------------------------------------------------------------------
__global__ void init_kernel() {
    int t = blockIdx.x * blockDim.x + threadIdx.x;
    if (t < K_CODES) g_counts[t] = 0;
    if (t == 0) g_mse = 0.0;
}

// znorm[n] = sum_d z[n,d]^2, sequential order, separate mul/add rounding
// (mimics (zf*zf).sum() — product materialized then summed)
__global__ void znorm_kernel(const float* __restrict__ z) {
    int n = blockIdx.x * blockDim.x + threadIdx.x;
    if (n >= N_Q) return;
    int b = n >> 10, hw = n & 1023;
    const float* p = z + (size_t)b * (D_DIM * HW) + hw;
    float s = 0.f;
#pragma unroll 8
    for (int d = 0; d < D_DIM; d++) {
        float v = p[(size_t)d * HW];
        s = __fadd_rn(s, __fmul_rn(v, v));
    }
    g_znorm[n] = s;
}

// enorm[k] = sum_d cb[k,d]^2  (value is far below ulp(256); any order fine)
__global__ void enorm_kernel(const float* __restrict__ cbk) {
    int code = blockIdx.x * 8 + (threadIdx.x >> 5);
    int lane = threadIdx.x & 31;
    const float* p = cbk + (size_t)code * D_DIM;
    float s = 0.f;
#pragma unroll
    for (int i = 0; i < 8; i++) {
        float v = p[i * 32 + lane];
        s = fmaf(v, v, s);
    }
#pragma unroll
    for (int o = 16; o > 0; o >>= 1)
        s += __shfl_xor_sync(0xffffffffu, s, o);
    if (lane == 0) g_enorm[code] = s;
}

// ---------------------------------------------------------------------------
// Main argmin kernel: block handles 64 queries vs all 8192 codes.
// dist replicates reference rounding: fl(fl(zn + en) - fl(2*dot)).
__global__ __launch_bounds__(NTHREADS)
void argmin_kernel(const float* __restrict__ z,
                   const float* __restrict__ cbk,
                   float* __restrict__ out) {
    extern __shared__ float smem[];
    float* As   = smem;                              // [256][64]
    float* Bs   = As + SMEM_AS_FLOATS;               // [64][128]
    float* s_en = Bs + SMEM_BS_FLOATS;               // [128]
    float* s_zn = s_en + BN;                         // [64]

    const int t  = threadIdx.x;
    const int tr = t >> 4;          // 0..15 query-row group
    const int tc = t & 15;          // 0..15 code-col group
    const int nbase = blockIdx.x * BM;
    const int b   = nbase >> 10;
    const int hw0 = nbase & 1023;
    const float* zbase = z + (size_t)b * (D_DIM * HW) + hw0;

    if (t < BM) s_zn[t] = g_znorm[nbase + t];

    // Load the block's full query tile once: As[d][m]
    {
        int m  = t & 63;
        int d0 = t >> 6;  // 0..3
#pragma unroll 16
        for (int i = 0; i < 64; i++) {
            int d = d0 + 4 * i;
            As[d * BM + m] = zbase[(size_t)d * HW + m];
        }
    }

    float bestv[TM];
    int   besti[TM];
#pragma unroll
    for (int i = 0; i < TM; i++) { bestv[i] = 3.4e38f; besti[i] = 0; }

    for (int ctile = 0; ctile < K_CODES; ctile += BN) {
        __syncthreads();   // prior epilogue done before s_en rewrite
        if (t < BN) s_en[t] = g_enorm[ctile + t];

        float acc[TM][TN];
#pragma unroll
        for (int i = 0; i < TM; i++)
#pragma unroll
            for (int j = 0; j < TN; j++) acc[i][j] = 0.f;

        for (int kb = 0; kb < D_DIM; kb += BK) {
            __syncthreads();  // protect Bs rewrite
            // Load Bs[k][n]: fully coalesced gmem, 8 lanes per code row
            {
                int lane8 = t & 7;
                int grp   = t >> 3;    // 0..31
#pragma unroll
                for (int pass = 0; pass < 4; pass++) {
                    int n2 = pass * 32 + grp;
                    const float4* src = reinterpret_cast<const float4*>(
                        cbk + (size_t)(ctile + n2) * D_DIM + kb);
#pragma unroll
                    for (int j = 0; j < 2; j++) {
                        float4 v = src[j * 8 + lane8];
                        int kk = j * 32 + lane8 * 4;
                        Bs[(kk + 0) * BN + n2] = v.x;
                        Bs[(kk + 1) * BN + n2] = v.y;
                        Bs[(kk + 2) * BN + n2] = v.z;
                        Bs[(kk + 3) * BN + n2] = v.w;
                    }
                }
            }
            __syncthreads();

#pragma unroll 4
            for (int k = 0; k < BK; k++) {
                const float4 av  = *reinterpret_cast<const float4*>(
                    &As[(kb + k) * BM + tr * TM]);
                const float4 bv0 = *reinterpret_cast<const float4*>(
                    &Bs[k * BN + tc * TN]);
                const float4 bv1 = *reinterpret_cast<const float4*>(
                    &Bs[k * BN + tc * TN + 4]);
                float a[TM]  = {av.x, av.y, av.z, av.w};
                float bb[TN] = {bv0.x, bv0.y, bv0.z, bv0.w,
                                bv1.x, bv1.y, bv1.z, bv1.w};
#pragma unroll
                for (int i = 0; i < TM; i++)
#pragma unroll
                    for (int j = 0; j < TN; j++)
                        acc[i][j] = fmaf(a[i], bb[j], acc[i][j]);
            }
        }

        // Epilogue: distance with reference-matching rounding, running argmin
#pragma unroll
        for (int i = 0; i < TM; i++) {
            float zn = s_zn[tr * TM + i];
#pragma unroll
            for (int j = 0; j < TN; j++) {
                int c = tc * TN + j;
                float dist = __fsub_rn(__fadd_rn(zn, s_en[c]),
                                       __fmul_rn(2.0f, acc[i][j]));
                if (dist < bestv[i]) { bestv[i] = dist; besti[i] = ctile + c; }
            }
        }
    }

    // Block reduction across the 16 code-column threads (reuse Bs space)
    __syncthreads();
    float* rval = Bs;                       // [64][16]
    int*   ridx = (int*)(Bs + BM * 16);     // [64][16]
#pragma unroll
    for (int i = 0; i < TM; i++) {
        rval[(tr * TM + i) * 16 + tc] = bestv[i];
        ridx[(tr * TM + i) * 16 + tc] = besti[i];
    }
    __syncthreads();
    if (t < BM) {
        float bv = rval[t * 16];
        int   bi = ridx[t * 16];
        for (int c = 1; c < 16; c++) {
            float v  = rval[t * 16 + c];
            int   ix = ridx[t * 16 + c];
            if (v < bv || (v == bv && ix < bi)) { bv = v; bi = ix; }
        }
        int n = nbase + t;
        g_bestidx[n] = bi;
        out[OFF_IDX + n] = (float)bi;
        atomicAdd(&g_counts[bi], 1);
    }
}

// ---------------------------------------------------------------------------
// Gather z_q (== z_q_st forward value) + accumulate MSE
__global__ void gather_kernel(const float* __restrict__ z,
                              const float* __restrict__ cbk,
                              float* __restrict__ out) {
    int o  = blockIdx.x * 256 + threadIdx.x;   // linear index into (B,D,H,W)
    int hw = o & 1023;
    int d  = (o >> 10) & 255;
    int b  = o >> 18;
    int n  = (b << 10) + hw;
    int idx = g_bestidx[n];
    float q  = cbk[(size_t)idx * D_DIM + d];
    out[o] = q;
    float diff = q - z[o];
    float sq = diff * diff;

    __shared__ float red[256];
    red[threadIdx.x] = sq;
    __syncthreads();
#pragma unroll
    for (int s = 128; s > 0; s >>= 1) {
        if (threadIdx.x < s) red[threadIdx.x] += red[threadIdx.x + s];
        __syncthreads();
    }
    if (threadIdx.x == 0) atomicAdd(&g_mse, (double)red[0]);
}

// ---------------------------------------------------------------------------
__global__ void finalize_kernel(float* __restrict__ out) {
    __shared__ double red[256];
    int t = threadIdx.x;
    double s = 0.0;
    for (int i = t; i < K_CODES; i += 256) {
        double p = (double)g_counts[i] * (1.0 / 16384.0);
        s += p * log(p + 1e-10);
    }
    red[t] = s;
    __syncthreads();
#pragma unroll
    for (int st = 128; st > 0; st >>= 1) {
        if (t < st) red[t] += red[t + st];
        __syncthreads();
    }
    if (t == 0) {
        double mse = g_mse / (double)Z_ELEMS;
        out[OFF_LOSS] = (float)(1.25 * mse);   // codebook + BETA*commitment
        out[OFF_PLX]  = (float)exp(-red[0]);
    }
}

// ---------------------------------------------------------------------------
extern "C" void kernel_launch(void* const* d_in, const int* in_sizes, int n_in,
                              void* d_out, int out_size) {
    const float* z   = (const float*)d_in[0];   // z_e (16,256,32,32)
    const float* cbk = (const float*)d_in[1];   // codebook (8192,256)
    float* out = (float*)d_out;

    cudaFuncSetAttribute(argmin_kernel,
                         cudaFuncAttributeMaxDynamicSharedMemorySize,
                         SMEM_BYTES);

    init_kernel<<<32, 256>>>();
    znorm_kernel<<<N_Q / 256, 256>>>(z);
    enorm_kernel<<<K_CODES / 8, 256>>>(cbk);
    argmin_kernel<<<N_Q / BM, NTHREADS, SMEM_BYTES>>>(z, cbk, out);
    gather_kernel<<<Z_ELEMS / 256, 256>>>(z, cbk, out);
    finalize_kernel<<<1, 256>>>(out);
}

// round 4
// speedup vs baseline: 2.5095x; 2.5095x over previous
#include <cuda_runtime.h>
#include <math.h>

// Problem constants
#define D_DIM   256
#define HW      1024
#define N_Q     16384
#define K_CODES 8192
#define Z_ELEMS 4194304

// Output layout (flattened tuple, float32)
#define OFF_LOSS 4194304
#define OFF_IDX  4194305
#define OFF_PLX  4210689

// Main-kernel tiling
#define QT   128    // queries per block
#define CC   512    // codes per block
#define CTW  128    // codes per smem tile (4 tiles per block)
#define BK   32     // k-chunk
#define NTH  128    // threads per block

// smem (floats): As[2][32][128] + Bs[2][32][128] + en[512] + zn[128]
#define SMEM_FLOATS (8192 + 8192 + 512 + 128)
#define SMEM_BYTES  (SMEM_FLOATS * 4)

// Device scratch (no cudaMalloc allowed)
__device__ float  g_cbT[D_DIM * K_CODES];        // transposed codebook, 8 MB
__device__ unsigned long long g_key[N_Q];        // packed (dist,idx) per query
__device__ float  g_enorm[K_CODES];
__device__ float  g_znorm[N_Q];
__device__ int    g_bestidx[N_Q];
__device__ int    g_counts[K_CODES];
__device__ double g_mse;

// ---------------------------------------------------------------------------
// Packed fp32x2 helpers (Blackwell FFMA2 path)
#define FMA2(acc, a, b) \
    asm("fma.rn.f32x2 %0, %1, %2, %0;" : "+l"(acc) : "l"(a), "l"(b))
#define DUP2(d, f) \
    asm("mov.b64 %0, {%1, %1};" : "=l"(d) : "r"(__float_as_uint(f)))
#define UNPACK2(lo, hi, v) \
    asm("mov.b64 {%0, %1}, %2;" : "=r"(lo), "=r"(hi) : "l"(v))

__device__ __forceinline__ void cp16(void* dst, const void* src) {
    unsigned s = (unsigned)__cvta_generic_to_shared(dst);
    asm volatile("cp.async.cg.shared.global [%0], [%1], 16;"
                 :: "r"(s), "l"(src) : "memory");
}

// ---------------------------------------------------------------------------
__global__ void init_kernel() {
    int t = blockIdx.x * blockDim.x + threadIdx.x;
    if (t < K_CODES) g_counts[t] = 0;
    if (t < N_Q)     g_key[t] = 0xFFFFFFFFFFFFFFFFull;
    if (t == 0)      g_mse = 0.0;
}

// Codebook transpose: g_cbT[d][k] = cb[k][d]
__global__ void transpose_kernel(const float* __restrict__ cb) {
    __shared__ float tile[32][33];
    int k0 = blockIdx.x * 32, d0 = blockIdx.y * 32;
    int x = threadIdx.x, y0 = threadIdx.y;
    for (int y = y0; y < 32; y += 8)
        tile[y][x] = cb[(size_t)(k0 + y) * D_DIM + d0 + x];
    __syncthreads();
    for (int y = y0; y < 32; y += 8)
        g_cbT[(size_t)(d0 + y) * K_CODES + k0 + x] = tile[x][y];
}

// znorm: sequential __fadd_rn(__fmul_rn) to mimic reference (zf*zf).sum()
__global__ void znorm_kernel(const float* __restrict__ z) {
    int n = blockIdx.x * blockDim.x + threadIdx.x;
    if (n >= N_Q) return;
    int b = n >> 10, hw = n & 1023;
    const float* p = z + (size_t)b * (D_DIM * HW) + hw;
    float s = 0.f;
#pragma unroll 8
    for (int d = 0; d < D_DIM; d++) {
        float v = p[(size_t)d * HW];
        s = __fadd_rn(s, __fmul_rn(v, v));
    }
    g_znorm[n] = s;
}

__global__ void enorm_kernel(const float* __restrict__ cbk) {
    int code = blockIdx.x * 8 + (threadIdx.x >> 5);
    int lane = threadIdx.x & 31;
    const float* p = cbk + (size_t)code * D_DIM;
    float s = 0.f;
#pragma unroll
    for (int i = 0; i < 8; i++) {
        float v = p[i * 32 + lane];
        s = fmaf(v, v, s);
    }
#pragma unroll
    for (int o = 16; o > 0; o >>= 1)
        s += __shfl_xor_sync(0xffffffffu, s, o);
    if (lane == 0) g_enorm[code] = s;
}

// ---------------------------------------------------------------------------
// Main kernel: block = 128 queries x 512 codes; FFMA2 inner loop.
// Thread layout: tn = tid&7 (16 codes), tm = tid>>3 (8 queries).
__global__ __launch_bounds__(NTH, 2)
void argmin_kernel(const float* __restrict__ z) {
    extern __shared__ float smem[];
    float* As   = smem;               // [2][32][128]
    float* Bs   = smem + 8192;        // [2][32][128]
    float* s_en = smem + 16384;       // [512]
    float* s_zn = s_en + 512;         // [128]

    const int tid = threadIdx.x;
    const int tn  = tid & 7;
    const int tm  = tid >> 3;
    const int bx  = blockIdx.x;
    const int qt  = bx >> 4;
    const int cch = bx & 15;
    const int q0     = qt << 7;
    const int cbase  = cch << 9;
    const int bb     = q0 >> 10;
    const int hw0    = q0 & 1023;
    const float* zbase = z + (size_t)bb * (D_DIM * HW) + hw0;

    s_zn[tid] = g_znorm[q0 + tid];
    for (int i = tid; i < CC; i += NTH) s_en[i] = g_enorm[cbase + i];

    float bestv[8]; int besti[8];
#pragma unroll
    for (int i = 0; i < 8; i++) { bestv[i] = 3.4e38f; besti[i] = 0; }

    for (int ct = 0; ct < CC / CTW; ct++) {
        const float* cbT = g_cbT + cbase + (ct << 7);

        unsigned long long acc[8][8];
#pragma unroll
        for (int i = 0; i < 8; i++)
#pragma unroll
            for (int j = 0; j < 8; j++) acc[i][j] = 0ull;

        // ---- stage loader: BK x 128 of A and B (one cp.async group) ----
        auto load_stage = [&](int kb, int s) {
            float* Ad = As + s * 4096;
            float* Bd = Bs + s * 4096;
#pragma unroll
            for (int i = 0; i < 8; i++) {
                int lin = tid + i * NTH;          // 0..1023
                int row = lin >> 5;                // 0..31
                int c   = (lin & 31) << 2;         // float offset, 16B granule
                const float* asrc = zbase + (size_t)((kb << 5) + row) * HW + c;
                const float* bsrc = cbT + (size_t)((kb << 5) + row) * K_CODES + c;
                cp16(Ad + row * 128 + c, asrc);
                cp16(Bd + row * 128 + c, bsrc);
            }
            asm volatile("cp.async.commit_group;");
        };

        load_stage(0, 0);

        for (int kb = 0; kb < D_DIM / BK; kb++) {
            if (kb < D_DIM / BK - 1) {
                load_stage(kb + 1, (kb + 1) & 1);
                asm volatile("cp.async.wait_group 1;");
            } else {
                asm volatile("cp.async.wait_group 0;");
            }
            __syncthreads();

            const float* Ak = As + (kb & 1) * 4096;
            const float* Bk = Bs + (kb & 1) * 4096;

#pragma unroll 8
            for (int k = 0; k < BK; k++) {
                const float* Ar = Ak + k * 128 + (tm << 3);
                const float* Br = Bk + k * 128 + (tn << 2);

                unsigned long long a2[8], b2[8];
                float4 a0 = *reinterpret_cast<const float4*>(Ar);
                float4 a1 = *reinterpret_cast<const float4*>(Ar + 4);
                DUP2(a2[0], a0.x); DUP2(a2[1], a0.y);
                DUP2(a2[2], a0.z); DUP2(a2[3], a0.w);
                DUP2(a2[4], a1.x); DUP2(a2[5], a1.y);
                DUP2(a2[6], a1.z); DUP2(a2[7], a1.w);

                b2[0] = *reinterpret_cast<const unsigned long long*>(Br + 0);
                b2[1] = *reinterpret_cast<const unsigned long long*>(Br + 2);
                b2[2] = *reinterpret_cast<const unsigned long long*>(Br + 32);
                b2[3] = *reinterpret_cast<const unsigned long long*>(Br + 34);
                b2[4] = *reinterpret_cast<const unsigned long long*>(Br + 64);
                b2[5] = *reinterpret_cast<const unsigned long long*>(Br + 66);
                b2[6] = *reinterpret_cast<const unsigned long long*>(Br + 96);
                b2[7] = *reinterpret_cast<const unsigned long long*>(Br + 98);

#pragma unroll
                for (int i = 0; i < 8; i++)
#pragma unroll
                    for (int j = 0; j < 8; j++)
                        FMA2(acc[i][j], a2[i], b2[j]);
            }
            __syncthreads();
        }

        // ---- epilogue: reference-rounded distance + running argmin ----
        const float* enct = s_en + (ct << 7);
#pragma unroll
        for (int i = 0; i < 8; i++) {
            float zn = s_zn[(tm << 3) + i];
#pragma unroll
            for (int j = 0; j < 8; j++) {
                unsigned lo, hi;
                UNPACK2(lo, hi, acc[i][j]);
                int cc = (tn << 2) + ((j >> 1) << 5) + ((j & 1) << 1);
                float d0 = __fsub_rn(__fadd_rn(zn, enct[cc]),
                                     __fmul_rn(2.0f, __uint_as_float(lo)));
                float d1 = __fsub_rn(__fadd_rn(zn, enct[cc + 1]),
                                     __fmul_rn(2.0f, __uint_as_float(hi)));
                int g = cbase + (ct << 7) + cc;
                if (d0 < bestv[i]) { bestv[i] = d0; besti[i] = g; }
                if (d1 < bestv[i]) { bestv[i] = d1; besti[i] = g + 1; }
            }
        }
    }

    // ---- block merge across the 8 tn-threads per query row ----
    __syncthreads();
    float* rv = As;                        // [128][8]
    int*   ri = (int*)(As + 1024);         // [128][8]
#pragma unroll
    for (int i = 0; i < 8; i++) {
        rv[((tm << 3) + i) * 8 + tn] = bestv[i];
        ri[((tm << 3) + i) * 8 + tn] = besti[i];
    }
    __syncthreads();
    {
        float bv = rv[tid * 8];
        int   bi = ri[tid * 8];
#pragma unroll
        for (int c = 1; c < 8; c++) {
            float v = rv[tid * 8 + c];
            int   x = ri[tid * 8 + c];
            if (v < bv || (v == bv && x < bi)) { bv = v; bi = x; }
        }
        // dist > 0 always (||z||^2 ~ 256 dominates) -> float bits monotonic
        unsigned long long key =
            ((unsigned long long)__float_as_uint(bv) << 32) | (unsigned)bi;
        atomicMin(&g_key[q0 + tid], key);
    }
}

// ---------------------------------------------------------------------------
__global__ void decode_kernel(float* __restrict__ out) {
    int n = blockIdx.x * 256 + threadIdx.x;
    unsigned long long key = g_key[n];
    int idx = (int)(unsigned)(key & 0xFFFFFFFFull);
    g_bestidx[n] = idx;
    out[OFF_IDX + n] = (float)idx;
    atomicAdd(&g_counts[idx], 1);
}

__global__ void gather_kernel(const float* __restrict__ z,
                              const float* __restrict__ cbk,
                              float* __restrict__ out) {
    int o  = blockIdx.x * 256 + threadIdx.x;
    int hw = o & 1023;
    int d  = (o >> 10) & 255;
    int b  = o >> 18;
    int n  = (b << 10) + hw;
    int idx = g_bestidx[n];
    float q = cbk[(size_t)idx * D_DIM + d];
    out[o] = q;
    float diff = q - z[o];
    float sq = diff * diff;

    __shared__ float red[256];
    red[threadIdx.x] = sq;
    __syncthreads();
#pragma unroll
    for (int s = 128; s > 0; s >>= 1) {
        if (threadIdx.x < s) red[threadIdx.x] += red[threadIdx.x + s];
        __syncthreads();
    }
    if (threadIdx.x == 0) atomicAdd(&g_mse, (double)red[0]);
}

__global__ void finalize_kernel(float* __restrict__ out) {
    __shared__ double red[256];
    int t = threadIdx.x;
    double s = 0.0;
    for (int i = t; i < K_CODES; i += 256) {
        double p = (double)g_counts[i] * (1.0 / 16384.0);
        s += p * log(p + 1e-10);
    }
    red[t] = s;
    __syncthreads();
#pragma unroll
    for (int st = 128; st > 0; st >>= 1) {
        if (t < st) red[t] += red[t + st];
        __syncthreads();
    }
    if (t == 0) {
        double mse = g_mse / (double)Z_ELEMS;
        out[OFF_LOSS] = (float)(1.25 * mse);
        out[OFF_PLX]  = (float)exp(-red[0]);
    }
}

// ---------------------------------------------------------------------------
extern "C" void kernel_launch(void* const* d_in, const int* in_sizes, int n_in,
                              void* d_out, int out_size) {
    const float* z   = (const float*)d_in[0];
    const float* cbk = (const float*)d_in[1];
    float* out = (float*)d_out;

    cudaFuncSetAttribute(argmin_kernel,
                         cudaFuncAttributeMaxDynamicSharedMemorySize,
                         SMEM_BYTES);

    init_kernel<<<N_Q / 256, 256>>>();
    transpose_kernel<<<dim3(K_CODES / 32, D_DIM / 32), dim3(32, 8)>>>(cbk);
    znorm_kernel<<<N_Q / 256, 256>>>(z);
    enorm_kernel<<<K_CODES / 8, 256>>>(cbk);
    argmin_kernel<<<(N_Q / QT) * (K_CODES / CC), NTH, SMEM_BYTES>>>(z);
    decode_kernel<<<N_Q / 256, 256>>>(out);
    gather_kernel<<<Z_ELEMS / 256, 256>>>(z, cbk, out);
    finalize_kernel<<<1, 256>>>(out);
}